// round 2
// baseline (speedup 1.0000x reference)
#include <cuda_runtime.h>
#include <cuda_bf16.h>

// Problem constants
#define NSPL 191               // 3*64 - 1 spline dims
#define KB   64                // bins

__device__ __forceinline__ float softplus_f(float x) {
    // stable: max(x,0) + log(1 + exp(-|x|))
    return fmaxf(x, 0.0f) + __logf(1.0f + __expf(-fabsf(x)));
}

__global__ __launch_bounds__(256)
void rqs_logdet_kernel(const float* __restrict__ value,
                       const float* __restrict__ delta_spline,
                       const int*   __restrict__ genes_oi,
                       const int*   __restrict__ local_gene_ix,
                       const float* __restrict__ spline_weight,
                       float*       __restrict__ out,
                       int n)
{
    const unsigned FULL = 0xffffffffu;
    const float WINDOW_A      = -10000.0f;
    const float INV_AB        = 1.0f / 20000.0f;
    const float MBW           = 0.001f;   // MIN_BIN_WIDTH
    const float MBH           = 0.001f;   // MIN_BIN_HEIGHT
    const float MDER          = 0.001f;   // MIN_DERIVATIVE
    const float DEFAULT_INIT  = 0.53974366f;  // log(exp(0.999)-1)
    const float OUT_CONST     = -0.69314718f - 9.90348755f; // LOG_HALF - LOG_AB
    const float cH            = 1.0f - MBH * KB;
    const float cW            = 1.0f - MBW * KB;

    int cut  = (int)((blockIdx.x * (unsigned)blockDim.x + threadIdx.x) >> 5);
    int lane = threadIdx.x & 31;
    if (cut >= n) return;   // warp-uniform

    const float* ds = delta_spline + (long long)cut * NSPL;
    int g = genes_oi[local_gene_ix[cut]];
    const float* sw = spline_weight + (long long)g * NSPL;

    // Adjacent-pair bin layout: lane L owns bins j0=2L, j1=2L+1
    int j0 = lane * 2;
    int j1 = j0 + 1;

    float uw0 = sw[j0]       + ds[j0];
    float uw1 = sw[j1]       + ds[j1];
    float uh0 = sw[64 + j0]  + ds[64 + j0];
    float uh1 = sw[64 + j1]  + ds[64 + j1];
    // ud_raw has 63 entries (spline[128..190]); lane L slots t=2L, 2L+1 (2L+1<=62)
    float udA = sw[128 + j0] + ds[128 + j0];
    float udB = (j1 <= 62) ? (sw[128 + j1] + ds[128 + j1]) : 0.0f;

    float v  = value[cut];
    float x  = ((v - WINDOW_A) * INV_AB - 0.5f) * 2.0f;
    bool inside = (x >= -1.0f) && (x <= 1.0f);
    float xc = fminf(fmaxf(x, -1.0f), 1.0f);

    float ew0 = __expf(uw0), ew1 = __expf(uw1);
    float eh0 = __expf(uh0), eh1 = __expf(uh1);

    // S_w = sum of exp(uw) over 64 bins (butterfly reduce)
    float Sw = ew0 + ew1;
    #pragma unroll
    for (int o = 16; o; o >>= 1) Sw += __shfl_xor_sync(FULL, Sw, o);

    // Inclusive Kogge-Stone scan of eh pair sums -> raw cum-exp at bin 2L+1
    float csp = eh0 + eh1;
    #pragma unroll
    for (int o = 1; o < 32; o <<= 1) {
        float nv = __shfl_up_sync(FULL, csp, o);
        if (lane >= o) csp += nv;
    }
    float Sh = __shfl_sync(FULL, csp, 31);
    float invSh = __fdividef(1.0f, Sh);

    // Normalized inclusive cumsum of softmax-heights at bins j0, j1:
    //   cs[j] = (j+1)*MBH + cH * cumexp[j] / Sh;   ch[j+1] = 2*cs[j] - 1
    float cs_odd  = (float)(j1 + 1) * MBH + cH * csp * invSh;
    float cs_even = (float)(j0 + 1) * MBH + cH * (csp - eh1) * invSh;

    // idx = #{ j in 1..64 : xc >= ch[j] }, clipped to 63 (xc >= ch[0]=-1 always)
    int cnt = (int)(xc >= 2.0f * cs_even - 1.0f) + (int)(xc >= 2.0f * cs_odd - 1.0f);
    #pragma unroll
    for (int o = 16; o; o >>= 1) cnt += __shfl_xor_sync(FULL, cnt, o);
    int idx = min(cnt, 63);   // warp-uniform

    // ---- gathers (idx uniform => single shfl each) ----
    // in_ch = left edge of bin idx = 2*cs[idx-1] - 1  (or -1 for idx==0)
    float in_ch;
    {
        int j = idx - 1;
        float cand = (j & 1) ? csp : (csp - eh1);   // raw cumexp at bin j on lane j>>1
        float craw = __shfl_sync(FULL, cand, (j >= 0) ? (j >> 1) : 0);
        float cs = (float)idx * MBH + cH * craw * invSh;
        in_ch = (idx == 0) ? -1.0f : (2.0f * cs - 1.0f);
    }
    float eh_sel = __shfl_sync(FULL, (idx & 1) ? eh1 : eh0, idx >> 1);
    float ew_sel = __shfl_sync(FULL, (idx & 1) ? ew1 : ew0, idx >> 1);
    float h_sm = MBH + cH * eh_sel * invSh;
    float w_sm = MBW + cW * __fdividef(ew_sel, Sw);
    float in_h = 2.0f * h_sm;
    float dlt  = __fdividef(h_sm, w_sm);   // (h/w)[idx]; x2 normalization cancels

    // derivatives at knots idx and idx+1 (ud_padded indexing)
    int t0 = idx - 1;                               // ud_raw index for d0
    float cand0 = (t0 & 1) ? udB : udA;
    float u0 = __shfl_sync(FULL, cand0, (t0 >= 0) ? (t0 >> 1) : 0);
    if (idx == 0) u0 = DEFAULT_INIT;
    float cand1 = (idx & 1) ? udB : udA;            // ud_raw index = idx (for d1)
    float u1 = __shfl_sync(FULL, cand1, idx >> 1);
    if (idx == 63) u1 = DEFAULT_INIT;

    float d0 = MDER + softplus_f(u0);
    float d1 = MDER + softplus_f(u1);

    // rational-quadratic inverse, logabsdet only
    float dy = xc - in_ch;
    float s  = d0 + d1 - 2.0f * dlt;
    float a  = dy * s + in_h * (dlt - d0);
    float b  = in_h * d0 - dy * s;
    float c  = -dlt * dy;
    float disc = b * b - 4.0f * a * c;
    float root = __fdividef(2.0f * c, -b - sqrtf(fmaxf(disc, 0.0f)));
    float tom  = root * (1.0f - root);
    float denom = dlt + s * tom;
    float omr  = 1.0f - root;
    float deriv_num = dlt * dlt * (d1 * root * root + 2.0f * dlt * tom + d0 * omr * omr);
    float logabsdet = -(__logf(deriv_num) - 2.0f * __logf(denom));

    float res = OUT_CONST + (inside ? logabsdet : 0.0f);
    if (lane == 0) out[cut] = res;
}

extern "C" void kernel_launch(void* const* d_in, const int* in_sizes, int n_in,
                              void* d_out, int out_size) {
    const float* value         = (const float*)d_in[0];
    const float* delta_spline  = (const float*)d_in[1];
    const int*   genes_oi      = (const int*)d_in[2];
    const int*   local_gene_ix = (const int*)d_in[3];
    const float* spline_weight = (const float*)d_in[4];
    float* out = (float*)d_out;
    int n = in_sizes[0];             // N_CUTS
    int warps_per_block = 8;         // 256 threads
    int blocks = (n + warps_per_block - 1) / warps_per_block;
    rqs_logdet_kernel<<<blocks, 256>>>(value, delta_spline, genes_oi,
                                       local_gene_ix, spline_weight, out, n);
}

// round 5
// speedup vs baseline: 1.3293x; 1.3293x over previous
#include <cuda_runtime.h>
#include <cuda_bf16.h>

// Problem constants
#define NSPL 191               // 3*64 - 1 spline dims
#define KB   64                // bins

__device__ __forceinline__ float softplus_f(float x) {
    // stable: max(x,0) + log(1 + exp(-|x|))
    return fmaxf(x, 0.0f) + __logf(1.0f + __expf(-fabsf(x)));
}

// 4 cuts per warp: lane = 8*g + s; group g handles cut warp*4+g,
// sublane s owns bins [8s, 8s+8).
__global__ __launch_bounds__(256)
void rqs_logdet4_kernel(const float* __restrict__ value,
                        const float* __restrict__ delta_spline,
                        const int*   __restrict__ genes_oi,
                        const int*   __restrict__ local_gene_ix,
                        const float* __restrict__ spline_weight,
                        float*       __restrict__ out,
                        int n)
{
    const unsigned FULL = 0xffffffffu;
    const float WINDOW_A      = -10000.0f;
    const float INV_AB        = 1.0f / 20000.0f;
    const float MBW           = 0.001f;
    const float MBH           = 0.001f;
    const float MDER          = 0.001f;
    const float DEFAULT_INIT  = 0.53974366f;               // log(exp(0.999)-1)
    const float OUT_CONST     = -0.69314718f - 9.90348755f; // LOG_HALF - LOG_AB
    const float cH            = 1.0f - MBH * KB;            // 0.936
    const float cW            = 1.0f - MBW * KB;

    const int lane = threadIdx.x & 31;
    const int g    = lane >> 3;
    const int s    = lane & 7;
    int warp = (int)((blockIdx.x * (unsigned)blockDim.x + threadIdx.x) >> 5);
    long long cut_base = (long long)warp * 4;
    if (cut_base >= n) return;                 // whole-warp uniform exit
    long long cutl = cut_base + g;
    bool active = (cutl < n);
    int cut = active ? (int)cutl : (n - 1);    // clamp; store is predicated

    const float* ds = delta_spline + (long long)cut * NSPL;
    int gene = genes_oi[local_gene_ix[cut]];
    const float* sw = spline_weight + (long long)gene * NSPL;

    const int jb = s * 8;

    // ---- per-bin phase: widths sum + heights local cumsum ----
    float cum[8];
    float Swl = 0.0f;
    float run = 0.0f;
    #pragma unroll
    for (int k = 0; k < 8; ++k) {
        int j = jb + k;
        float uw = ds[j]      + sw[j];
        float uh = ds[KB + j] + sw[KB + j];
        Swl += __expf(uw);
        run += __expf(uh);
        cum[k] = run;
    }

    // ---- cross-lane (width-8) exclusive scan of lane totals ----
    float incl = run;
    #pragma unroll
    for (int o = 1; o < 8; o <<= 1) {
        float u = __shfl_up_sync(FULL, incl, o, 8);
        if (s >= o) incl += u;
    }
    float excl = incl - run;
    float Sh = __shfl_sync(FULL, incl, 7, 8);     // group total
    #pragma unroll
    for (int k = 0; k < 8; ++k) cum[k] += excl;   // global inclusive cumexp

    // ---- widths total (width-8 butterfly) ----
    #pragma unroll
    for (int o = 4; o; o >>= 1) Swl += __shfl_xor_sync(FULL, Swl, o, 8);

    // ---- x ----
    float v  = value[cut];
    float x  = ((v - WINDOW_A) * INV_AB - 0.5f) * 2.0f;
    bool inside = (x >= -1.0f) && (x <= 1.0f);
    float xc = fminf(fmaxf(x, -1.0f), 1.0f);

    // ---- bin search: count bins j with ch[j+1] <= xc ----
    // xc >= 2*((j+1)*MBH + cH*cum[j]/Sh) - 1  <=>  cum[j] <= ((xc+1)/2-(j+1)*MBH)*Sh/cH
    float invSh = __fdividef(1.0f, Sh);
    float ShocH = Sh * (1.0f / cH);
    float stepl = MBH * ShocH;
    float R = (fmaf(xc, 0.5f, 0.5f) - (float)(jb + 1) * MBH) * ShocH;
    int cnt = 0;
    #pragma unroll
    for (int k = 0; k < 8; ++k) {
        cnt += (cum[k] <= R);
        R -= stepl;
    }
    #pragma unroll
    for (int o = 4; o; o >>= 1) cnt += __shfl_xor_sync(FULL, cnt, o, 8);
    int idx = min(cnt, 63);                       // group-uniform

    // ---- gather cum[idx-1] via one 8-way register tree + width-8 shfl ----
    int p  = idx - 1;
    int r2 = p & 7;
    int sl2 = (p >= 0) ? (p >> 3) : 0;
    float a01 = (r2 & 1) ? cum[1] : cum[0];
    float a23 = (r2 & 1) ? cum[3] : cum[2];
    float a45 = (r2 & 1) ? cum[5] : cum[4];
    float a67 = (r2 & 1) ? cum[7] : cum[6];
    float b0  = (r2 & 2) ? a23 : a01;
    float b1  = (r2 & 2) ? a67 : a45;
    float csel = (r2 & 4) ? b1 : b0;
    float c0 = __shfl_sync(FULL, csel, sl2, 8);
    if (idx == 0) c0 = 0.0f;

    // ---- recompute exp at idx (L1-hot reload, group-uniform address) ----
    float ew_g = __expf(ds[idx]      + sw[idx]);
    float eh_g = __expf(ds[KB + idx] + sw[KB + idx]);

    // ---- derivatives: load only the 2 needed slots (ud region never streamed) ----
    int i0 = max(idx - 1, 0);
    int i1 = min(idx, 62);
    float u0 = ds[2 * KB + i0] + sw[2 * KB + i0];
    float u1 = ds[2 * KB + i1] + sw[2 * KB + i1];
    if (idx == 0)  u0 = DEFAULT_INIT;
    if (idx == 63) u1 = DEFAULT_INIT;
    float d0 = MDER + softplus_f(u0);
    float d1 = MDER + softplus_f(u1);

    // ---- spline quantities at idx ----
    float h_sm = fmaf(cH * invSh, eh_g, MBH);
    float w_sm = fmaf(cW, __fdividef(ew_g, Swl), MBW);
    float in_h = 2.0f * h_sm;
    float dlt  = __fdividef(h_sm, w_sm);            // (h/w)[idx]
    float in_ch = fmaf(2.0f, fmaf(cH * invSh, c0, (float)idx * MBH), -1.0f);

    // ---- rational-quadratic inverse, logabsdet only ----
    float dy = xc - in_ch;
    float sc = d0 + d1 - 2.0f * dlt;
    float a  = dy * sc + in_h * (dlt - d0);
    float b  = in_h * d0 - dy * sc;
    float c  = -dlt * dy;
    float disc = b * b - 4.0f * a * c;
    float root = __fdividef(2.0f * c, -b - sqrtf(fmaxf(disc, 0.0f)));
    float tom  = root * (1.0f - root);
    float denom = dlt + sc * tom;
    float omr  = 1.0f - root;
    float deriv_num = dlt * dlt * (d1 * root * root + 2.0f * dlt * tom + d0 * omr * omr);
    float logabsdet = -(__logf(deriv_num) - 2.0f * __logf(denom));

    float res = OUT_CONST + (inside ? logabsdet : 0.0f);
    if (s == 0 && active) out[cut] = res;          // 4 consecutive floats / warp
}

extern "C" void kernel_launch(void* const* d_in, const int* in_sizes, int n_in,
                              void* d_out, int out_size) {
    const float* value         = (const float*)d_in[0];
    const float* delta_spline  = (const float*)d_in[1];
    const int*   genes_oi      = (const int*)d_in[2];
    const int*   local_gene_ix = (const int*)d_in[3];
    const float* spline_weight = (const float*)d_in[4];
    float* out = (float*)d_out;
    int n = in_sizes[0];                      // N_CUTS
    // 256 threads = 8 warps = 32 cuts per block
    int blocks = (n + 31) / 32;
    rqs_logdet4_kernel<<<blocks, 256>>>(value, delta_spline, genes_oi,
                                        local_gene_ix, spline_weight, out, n);
}